// round 1
// baseline (speedup 1.0000x reference)
#include <cuda_runtime.h>
#include <cuda_bf16.h>

// Problem constants
#define BB    16
#define NW    100
#define LL    64
#define CC    256
#define HH    8
#define DH    32
#define LOGIT_MAX 4.6051701859880913680f  // log(100)

// x occupies the first B*NW*L*C floats of d_out, attn follows.
#define X_TOTAL (BB * NW * LL * CC)          // 26,214,400

// One CTA per (b, window, head) tile.
// 256 threads arranged 16x16: thread (ty, tx) owns S rows 4*ty..4*ty+3,
// cols 4*tx..4*tx+3.  Softmax rows reduce across the 16 tx lanes, which are
// contiguous half-warp lanes, so __shfl_xor over offsets 8,4,2,1 stays in-group.
__global__ __launch_bounds__(256, 3)
void tat_window_attention_kernel(const float* __restrict__ q,
                                 const float* __restrict__ k,
                                 const float* __restrict__ v,
                                 const float* __restrict__ pos,
                                 const float* __restrict__ ls,
                                 float* __restrict__ out)
{
    __shared__ float Qs[LL][DH + 1];   // +1 pad: 2 ty-groups land in different banks
    __shared__ float Ks[LL][DH + 1];
    __shared__ float Vs[LL][DH + 1];
    __shared__ float Ps[LL][LL + 1];

    const int h = blockIdx.x;
    const int w = blockIdx.y;
    const int b = blockIdx.z;
    const int tid = threadIdx.x;
    const int tx = tid & 15;
    const int ty = tid >> 4;

    const long base_qkv = ((long)(b * NW + w) * LL) * CC + h * DH;
    const float* qp = q + base_qkv;
    const float* kp = k + base_qkv;
    const float* vp = v + base_qkv;
    const float* pp = pos + ((long)(b * HH + h) * LL) * LL;

    // ---- load Q/K/V head-slices (64 rows x 32 contiguous floats each) ----
    // 512 float4s per tensor, 256 threads -> 2 iterations, fully coalesced.
    #pragma unroll
    for (int it = 0; it < 2; it++) {
        int i  = tid + it * 256;
        int r  = i >> 3;
        int d4 = (i & 7) << 2;
        float4 aq = *(const float4*)(qp + r * CC + d4);
        Qs[r][d4 + 0] = aq.x; Qs[r][d4 + 1] = aq.y;
        Qs[r][d4 + 2] = aq.z; Qs[r][d4 + 3] = aq.w;
        float4 ak = *(const float4*)(kp + r * CC + d4);
        Ks[r][d4 + 0] = ak.x; Ks[r][d4 + 1] = ak.y;
        Ks[r][d4 + 2] = ak.z; Ks[r][d4 + 3] = ak.w;
        float4 av = *(const float4*)(vp + r * CC + d4);
        Vs[r][d4 + 0] = av.x; Vs[r][d4 + 1] = av.y;
        Vs[r][d4 + 2] = av.z; Vs[r][d4 + 3] = av.w;
    }

    const float scale = __expf(fminf(ls[h], LOGIT_MAX));
    __syncthreads();

    // ---- S = Q K^T  (64x64x32), 4x4 register tile per thread ----
    float acc[4][4] = {};
    #pragma unroll 8
    for (int kk = 0; kk < DH; kk++) {
        float a[4], bb2[4];
        #pragma unroll
        for (int i = 0; i < 4; i++) a[i]  = Qs[4 * ty + i][kk];
        #pragma unroll
        for (int j = 0; j < 4; j++) bb2[j] = Ks[4 * tx + j][kk];
        #pragma unroll
        for (int i = 0; i < 4; i++)
            #pragma unroll
            for (int j = 0; j < 4; j++)
                acc[i][j] = fmaf(a[i], bb2[j], acc[i][j]);
    }

    // ---- scale + position bias + row softmax, write attn ----
    float* attn_out = out + X_TOTAL +
                      (((long)(b * NW + w) * HH + h) * LL) * LL;
    #pragma unroll
    for (int i = 0; i < 4; i++) {
        const int row = 4 * ty + i;
        float4 p4 = *(const float4*)(pp + row * LL + 4 * tx);
        float s0 = fmaf(acc[i][0], scale, p4.x);
        float s1 = fmaf(acc[i][1], scale, p4.y);
        float s2 = fmaf(acc[i][2], scale, p4.z);
        float s3 = fmaf(acc[i][3], scale, p4.w);

        float m = fmaxf(fmaxf(s0, s1), fmaxf(s2, s3));
        #pragma unroll
        for (int o = 8; o >= 1; o >>= 1)
            m = fmaxf(m, __shfl_xor_sync(0xffffffffu, m, o));

        float e0 = __expf(s0 - m);
        float e1 = __expf(s1 - m);
        float e2 = __expf(s2 - m);
        float e3 = __expf(s3 - m);
        float sum = (e0 + e1) + (e2 + e3);
        #pragma unroll
        for (int o = 8; o >= 1; o >>= 1)
            sum += __shfl_xor_sync(0xffffffffu, sum, o);

        const float rinv = __fdividef(1.0f, sum);
        e0 *= rinv; e1 *= rinv; e2 *= rinv; e3 *= rinv;

        float4 pw = make_float4(e0, e1, e2, e3);
        *(float4*)(attn_out + row * LL + 4 * tx) = pw;

        Ps[row][4 * tx + 0] = e0;
        Ps[row][4 * tx + 1] = e1;
        Ps[row][4 * tx + 2] = e2;
        Ps[row][4 * tx + 3] = e3;
    }
    __syncthreads();

    // ---- O = P V  (64x32x64), 4 rows x 2 cols per thread ----
    float oacc[4][2] = {};
    #pragma unroll 8
    for (int kk = 0; kk < LL; kk++) {
        float a[4];
        #pragma unroll
        for (int i = 0; i < 4; i++) a[i] = Ps[4 * ty + i][kk];
        const float b0 = Vs[kk][2 * tx + 0];
        const float b1 = Vs[kk][2 * tx + 1];
        #pragma unroll
        for (int i = 0; i < 4; i++) {
            oacc[i][0] = fmaf(a[i], b0, oacc[i][0]);
            oacc[i][1] = fmaf(a[i], b1, oacc[i][1]);
        }
    }

    float* xo = out + base_qkv;
    #pragma unroll
    for (int i = 0; i < 4; i++) {
        const int row = 4 * ty + i;
        float2 t = make_float2(oacc[i][0], oacc[i][1]);
        *(float2*)(xo + row * CC + 2 * tx) = t;
    }
}

extern "C" void kernel_launch(void* const* d_in, const int* in_sizes, int n_in,
                              void* d_out, int out_size)
{
    const float* q   = (const float*)d_in[0];
    const float* k   = (const float*)d_in[1];
    const float* v   = (const float*)d_in[2];
    const float* pos = (const float*)d_in[3];
    const float* ls  = (const float*)d_in[4];
    float* out = (float*)d_out;

    dim3 grid(HH, NW, BB);   // (8, 100, 16) -> 12800 CTAs
    dim3 block(256);
    tat_window_attention_kernel<<<grid, block>>>(q, k, v, pos, ls, out);
}

// round 3
// speedup vs baseline: 1.4693x; 1.4693x over previous
#include <cuda_runtime.h>
#include <cuda_bf16.h>
#include <cstdint>

#define BB 16
#define NW 100
#define HH 8
#define LLEN 64
#define CC 256
#define DH 32
#define LOGIT_MAX 4.6051701859880913680f
#define X_TOTAL (BB*NW*LLEN*CC)

#define QK_STRIDE 36   // bf16 units; conflict-free for fragment loads
#define VT_STRIDE 72   // bf16 units; conflict-free for fragment loads

__device__ __forceinline__ uint32_t pack2(float a, float b) {
    __nv_bfloat162 h = __floats2bfloat162_rn(a, b);
    return *reinterpret_cast<uint32_t*>(&h);
}
__device__ __forceinline__ float2 unpack2(uint32_t u) {
    return __bfloat1622float2(*reinterpret_cast<__nv_bfloat162*>(&u));
}

__device__ __forceinline__ void mma16816(float* c, const uint32_t* a, const uint32_t* b) {
    asm volatile(
        "mma.sync.aligned.m16n8k16.row.col.f32.bf16.bf16.f32 "
        "{%0,%1,%2,%3}, {%4,%5,%6,%7}, {%8,%9}, {%0,%1,%2,%3};"
        : "+f"(c[0]), "+f"(c[1]), "+f"(c[2]), "+f"(c[3])
        : "r"(a[0]), "r"(a[1]), "r"(a[2]), "r"(a[3]), "r"(b[0]), "r"(b[1]));
}

__global__ __launch_bounds__(128)
void tat_hmma_kernel(const float* __restrict__ q, const float* __restrict__ k,
                     const float* __restrict__ v, const float* __restrict__ pos,
                     const float* __restrict__ ls, float* __restrict__ out)
{
    __shared__ __nv_bfloat16 Qhi[LLEN][QK_STRIDE], Qlo[LLEN][QK_STRIDE];
    __shared__ __nv_bfloat16 Khi[LLEN][QK_STRIDE], Klo[LLEN][QK_STRIDE];
    __shared__ __nv_bfloat16 Vthi[DH][VT_STRIDE], Vtlo[DH][VT_STRIDE];

    const int h   = blockIdx.x;
    const int w   = blockIdx.y;
    const int b   = blockIdx.z;
    const int tid = threadIdx.x;
    const int wid = tid >> 5;
    const int lane = tid & 31;
    const int g = lane >> 2;     // group 0..7
    const int t = lane & 3;      // thread-in-group

    const long qkvbase = (long)(b * NW + w) * LLEN * CC;
    const float* qh = q + qkvbase + h * DH;
    const float* kh = k + qkvbase + h * DH;
    const float* vh = v + qkvbase + h * DH;

    // ---- stage Q, K (row-major) and V (transposed) in bf16 hi/lo ----
    #pragma unroll
    for (int i = 0; i < 4; i++) {
        int idx = tid + 128 * i;         // 0..511
        int r  = idx >> 3;               // 0..63
        int c4 = (idx & 7) * 4;          // 0..28
        float4 qv = *(const float4*)(qh + (long)r * CC + c4);
        float4 kv = *(const float4*)(kh + (long)r * CC + c4);
        float4 vv = *(const float4*)(vh + (long)r * CC + c4);
        #pragma unroll
        for (int j = 0; j < 4; j++) {
            float qx = (j == 0) ? qv.x : (j == 1) ? qv.y : (j == 2) ? qv.z : qv.w;
            float kx = (j == 0) ? kv.x : (j == 1) ? kv.y : (j == 2) ? kv.z : kv.w;
            float vx = (j == 0) ? vv.x : (j == 1) ? vv.y : (j == 2) ? vv.z : vv.w;
            __nv_bfloat16 qH = __float2bfloat16_rn(qx);
            __nv_bfloat16 kH = __float2bfloat16_rn(kx);
            __nv_bfloat16 vH = __float2bfloat16_rn(vx);
            Qhi[r][c4 + j] = qH;
            Qlo[r][c4 + j] = __float2bfloat16_rn(qx - __bfloat162float(qH));
            Khi[r][c4 + j] = kH;
            Klo[r][c4 + j] = __float2bfloat16_rn(kx - __bfloat162float(kH));
            Vthi[c4 + j][r] = vH;
            Vtlo[c4 + j][r] = __float2bfloat16_rn(vx - __bfloat162float(vH));
        }
    }
    __syncthreads();

    // ---- S = Q K^T (64x64x32): warp owns rows m0..m0+15 ----
    const int m0 = wid * 16;
    const int r0 = m0 + g;
    const int r1 = r0 + 8;

    uint32_t aHi[2][4], aLo[2][4];
    #pragma unroll
    for (int ks = 0; ks < 2; ks++) {
        int kc = ks * 16 + t * 2;
        aHi[ks][0] = *(const uint32_t*)&Qhi[r0][kc];
        aHi[ks][1] = *(const uint32_t*)&Qhi[r1][kc];
        aHi[ks][2] = *(const uint32_t*)&Qhi[r0][kc + 8];
        aHi[ks][3] = *(const uint32_t*)&Qhi[r1][kc + 8];
        aLo[ks][0] = *(const uint32_t*)&Qlo[r0][kc];
        aLo[ks][1] = *(const uint32_t*)&Qlo[r1][kc];
        aLo[ks][2] = *(const uint32_t*)&Qlo[r0][kc + 8];
        aLo[ks][3] = *(const uint32_t*)&Qlo[r1][kc + 8];
    }

    float s[8][4];
    #pragma unroll
    for (int j = 0; j < 8; j++)
        #pragma unroll
        for (int c = 0; c < 4; c++) s[j][c] = 0.0f;

    #pragma unroll
    for (int j = 0; j < 8; j++) {
        const int n = j * 8 + g;
        uint32_t bH[2][2], bL[2][2];
        #pragma unroll
        for (int ks = 0; ks < 2; ks++) {
            int kc = ks * 16 + t * 2;
            bH[ks][0] = *(const uint32_t*)&Khi[n][kc];
            bH[ks][1] = *(const uint32_t*)&Khi[n][kc + 8];
            bL[ks][0] = *(const uint32_t*)&Klo[n][kc];
            bL[ks][1] = *(const uint32_t*)&Klo[n][kc + 8];
        }
        #pragma unroll
        for (int ks = 0; ks < 2; ks++) mma16816(s[j], aHi[ks], bH[ks]);
        #pragma unroll
        for (int ks = 0; ks < 2; ks++) mma16816(s[j], aHi[ks], bL[ks]);
        #pragma unroll
        for (int ks = 0; ks < 2; ks++) mma16816(s[j], aLo[ks], bH[ks]);
    }

    // ---- scale + position + softmax (rows r0, r1) ----
    const float sc = __expf(fminf(__ldg(ls + h), LOGIT_MAX));
    const float* pb = pos + ((long)(b * HH + h) * LLEN) * LLEN;

    float mx0 = -1e30f, mx1 = -1e30f;
    #pragma unroll
    for (int j = 0; j < 8; j++) {
        float2 p0 = *(const float2*)(pb + r0 * LLEN + j * 8 + t * 2);
        float2 p1 = *(const float2*)(pb + r1 * LLEN + j * 8 + t * 2);
        s[j][0] = fmaf(s[j][0], sc, p0.x);
        s[j][1] = fmaf(s[j][1], sc, p0.y);
        s[j][2] = fmaf(s[j][2], sc, p1.x);
        s[j][3] = fmaf(s[j][3], sc, p1.y);
        mx0 = fmaxf(mx0, fmaxf(s[j][0], s[j][1]));
        mx1 = fmaxf(mx1, fmaxf(s[j][2], s[j][3]));
    }
    mx0 = fmaxf(mx0, __shfl_xor_sync(0xffffffffu, mx0, 1));
    mx0 = fmaxf(mx0, __shfl_xor_sync(0xffffffffu, mx0, 2));
    mx1 = fmaxf(mx1, __shfl_xor_sync(0xffffffffu, mx1, 1));
    mx1 = fmaxf(mx1, __shfl_xor_sync(0xffffffffu, mx1, 2));

    float sum0 = 0.0f, sum1 = 0.0f;
    #pragma unroll
    for (int j = 0; j < 8; j++) {
        s[j][0] = __expf(s[j][0] - mx0);
        s[j][1] = __expf(s[j][1] - mx0);
        s[j][2] = __expf(s[j][2] - mx1);
        s[j][3] = __expf(s[j][3] - mx1);
        sum0 += s[j][0] + s[j][1];
        sum1 += s[j][2] + s[j][3];
    }
    sum0 += __shfl_xor_sync(0xffffffffu, sum0, 1);
    sum0 += __shfl_xor_sync(0xffffffffu, sum0, 2);
    sum1 += __shfl_xor_sync(0xffffffffu, sum1, 1);
    sum1 += __shfl_xor_sync(0xffffffffu, sum1, 2);
    const float inv0 = __fdividef(1.0f, sum0);
    const float inv1 = __fdividef(1.0f, sum1);

    // normalize + write attn directly (fp32 exact)
    float* attn = out + X_TOTAL + ((long)((b * NW + w) * HH + h)) * (LLEN * LLEN);
    #pragma unroll
    for (int j = 0; j < 8; j++) {
        s[j][0] *= inv0; s[j][1] *= inv0;
        s[j][2] *= inv1; s[j][3] *= inv1;
        *(float2*)(attn + r0 * LLEN + j * 8 + t * 2) = make_float2(s[j][0], s[j][1]);
        *(float2*)(attn + r1 * LLEN + j * 8 + t * 2) = make_float2(s[j][2], s[j][3]);
    }

    // ---- repack P fragments (C-layout == A-layout) with hi/lo split ----
    uint32_t pHi[4][4], pLo[4][4];
    #pragma unroll
    for (int kk = 0; kk < 4; kk++) {
        const int j0 = 2 * kk, j1 = 2 * kk + 1;
        pHi[kk][0] = pack2(s[j0][0], s[j0][1]);
        pHi[kk][1] = pack2(s[j0][2], s[j0][3]);
        pHi[kk][2] = pack2(s[j1][0], s[j1][1]);
        pHi[kk][3] = pack2(s[j1][2], s[j1][3]);
        float2 f;
        f = unpack2(pHi[kk][0]); pLo[kk][0] = pack2(s[j0][0] - f.x, s[j0][1] - f.y);
        f = unpack2(pHi[kk][1]); pLo[kk][1] = pack2(s[j0][2] - f.x, s[j0][3] - f.y);
        f = unpack2(pHi[kk][2]); pLo[kk][2] = pack2(s[j1][0] - f.x, s[j1][1] - f.y);
        f = unpack2(pHi[kk][3]); pLo[kk][3] = pack2(s[j1][2] - f.x, s[j1][3] - f.y);
    }

    // ---- O = P V (64x32x64) ----
    float* xo = out + qkvbase + h * DH;
    #pragma unroll
    for (int jd = 0; jd < 4; jd++) {
        float o[4] = {0.0f, 0.0f, 0.0f, 0.0f};
        const int d = jd * 8 + g;
        #pragma unroll
        for (int kk = 0; kk < 4; kk++) {
            const int kc = kk * 16 + t * 2;
            uint32_t bH[2], bL[2];
            bH[0] = *(const uint32_t*)&Vthi[d][kc];
            bH[1] = *(const uint32_t*)&Vthi[d][kc + 8];
            bL[0] = *(const uint32_t*)&Vtlo[d][kc];
            bL[1] = *(const uint32_t*)&Vtlo[d][kc + 8];
            mma16816(o, pHi[kk], bH);
            mma16816(o, pHi[kk], bL);
            mma16816(o, pLo[kk], bH);
        }
        *(float2*)(xo + (long)r0 * CC + jd * 8 + t * 2) = make_float2(o[0], o[1]);
        *(float2*)(xo + (long)r1 * CC + jd * 8 + t * 2) = make_float2(o[2], o[3]);
    }
}

extern "C" void kernel_launch(void* const* d_in, const int* in_sizes, int n_in,
                              void* d_out, int out_size)
{
    const float* q   = (const float*)d_in[0];
    const float* k   = (const float*)d_in[1];
    const float* v   = (const float*)d_in[2];
    const float* pos = (const float*)d_in[3];
    const float* ls  = (const float*)d_in[4];
    float* out = (float*)d_out;

    dim3 grid(HH, NW, BB);   // 12800 CTAs
    tat_hmma_kernel<<<grid, 128>>>(q, k, v, pos, ls, out);
}

// round 6
// speedup vs baseline: 1.9692x; 1.3402x over previous
#include <cuda_runtime.h>
#include <cuda_bf16.h>
#include <cstdint>

#define BB 16
#define NW 100
#define HH 8
#define LLEN 64
#define CC 256
#define DH 32
#define LOGIT_MAX 4.6051701859880913680f
#define X_TOTAL (BB*NW*LLEN*CC)

#define ST 40   // bf16 units per smem row (80B): LDSM 8-row phases conflict-free

__device__ __forceinline__ uint32_t smem_u32(const void* p) {
    uint32_t a;
    asm("{ .reg .u64 t; cvta.to.shared.u64 t, %1; cvt.u32.u64 %0, t; }" : "=r"(a) : "l"(p));
    return a;
}

__device__ __forceinline__ uint32_t pack2(float a, float b) {
    __nv_bfloat162 h = __floats2bfloat162_rn(a, b);
    return *reinterpret_cast<uint32_t*>(&h);
}
__device__ __forceinline__ float2 unpack2(uint32_t u) {
    return __bfloat1622float2(*reinterpret_cast<__nv_bfloat162*>(&u));
}

// split 4 floats into packed bf16 hi (uint2) and lo (uint2)
__device__ __forceinline__ void split4(float4 xv, uint2& hi, uint2& lo) {
    hi.x = pack2(xv.x, xv.y);
    hi.y = pack2(xv.z, xv.w);
    float2 f01 = unpack2(hi.x);
    float2 f23 = unpack2(hi.y);
    lo.x = pack2(xv.x - f01.x, xv.y - f01.y);
    lo.y = pack2(xv.z - f23.x, xv.w - f23.y);
}

__device__ __forceinline__ void mma16816(float* c, const uint32_t* a,
                                         uint32_t b0, uint32_t b1) {
    asm volatile(
        "mma.sync.aligned.m16n8k16.row.col.f32.bf16.bf16.f32 "
        "{%0,%1,%2,%3}, {%4,%5,%6,%7}, {%8,%9}, {%0,%1,%2,%3};"
        : "+f"(c[0]), "+f"(c[1]), "+f"(c[2]), "+f"(c[3])
        : "r"(a[0]), "r"(a[1]), "r"(a[2]), "r"(a[3]), "r"(b0), "r"(b1));
}

__device__ __forceinline__ void ldsm4(uint32_t* r, uint32_t addr) {
    asm volatile("ldmatrix.sync.aligned.m8n8.x4.shared.b16 {%0,%1,%2,%3}, [%4];"
                 : "=r"(r[0]), "=r"(r[1]), "=r"(r[2]), "=r"(r[3]) : "r"(addr));
}
__device__ __forceinline__ void ldsm4t(uint32_t* r, uint32_t addr) {
    asm volatile("ldmatrix.sync.aligned.m8n8.x4.trans.shared.b16 {%0,%1,%2,%3}, [%4];"
                 : "=r"(r[0]), "=r"(r[1]), "=r"(r[2]), "=r"(r[3]) : "r"(addr));
}

// lane address for a 16x16 bf16 tile at (row0, byte col0) in a stride-80B buffer
__device__ __forceinline__ uint32_t tile_addr(uint32_t base, int lane, int row0, int col0) {
    int mat = lane >> 3, lr = lane & 7;
    int row = row0 + lr + ((mat & 1) << 3);
    int col = col0 + ((mat >> 1) << 4);
    return base + row * (ST * 2) + col;
}

__global__ __launch_bounds__(128)
void tat_hmma_kernel(const float* __restrict__ q, const float* __restrict__ k,
                     const float* __restrict__ v, const float* __restrict__ pos,
                     const float* __restrict__ ls, float* __restrict__ out)
{
    __shared__ __nv_bfloat16 Qhi[LLEN * ST], Qlo[LLEN * ST];
    __shared__ __nv_bfloat16 Khi[LLEN * ST], Klo[LLEN * ST];
    __shared__ __nv_bfloat16 Vhi[LLEN * ST], Vlo[LLEN * ST];   // row-major [k][d]

    const int h   = blockIdx.x;
    const int w   = blockIdx.y;
    const int b   = blockIdx.z;
    const int tid = threadIdx.x;
    const int wid = tid >> 5;
    const int lane = tid & 31;
    const int g = lane >> 2;
    const int t = lane & 3;

    const long qkvbase = (long)(b * NW + w) * LLEN * CC;
    const float* qh = q + qkvbase + h * DH;
    const float* kh = k + qkvbase + h * DH;
    const float* vh = v + qkvbase + h * DH;

    // ---- stage Q, K, V (all row-major) in packed bf16 hi/lo ----
    #pragma unroll
    for (int i = 0; i < 4; i++) {
        int idx = tid + 128 * i;         // 0..511
        int r  = idx >> 3;               // 0..63
        int c4 = (idx & 7) * 4;          // 0..28
        float4 qv = *(const float4*)(qh + (long)r * CC + c4);
        float4 kv = *(const float4*)(kh + (long)r * CC + c4);
        float4 vv = *(const float4*)(vh + (long)r * CC + c4);
        uint2 hi, lo;
        split4(qv, hi, lo);
        *(uint2*)&Qhi[r * ST + c4] = hi;
        *(uint2*)&Qlo[r * ST + c4] = lo;
        split4(kv, hi, lo);
        *(uint2*)&Khi[r * ST + c4] = hi;
        *(uint2*)&Klo[r * ST + c4] = lo;
        split4(vv, hi, lo);
        *(uint2*)&Vhi[r * ST + c4] = hi;
        *(uint2*)&Vlo[r * ST + c4] = lo;
    }
    __syncthreads();

    const uint32_t sQh = smem_u32(Qhi), sQl = smem_u32(Qlo);
    const uint32_t sKh = smem_u32(Khi), sKl = smem_u32(Klo);
    const uint32_t sVh = smem_u32(Vhi), sVl = smem_u32(Vlo);

    // ---- S = Q K^T (64x64x32), warp owns rows m0..m0+15 ----
    const int m0 = wid * 16;
    const int r0 = m0 + g;
    const int r1 = r0 + 8;

    uint32_t aH[2][4], aL[2][4];
    #pragma unroll
    for (int ks = 0; ks < 2; ks++) {
        ldsm4(aH[ks], tile_addr(sQh, lane, m0, 32 * ks));
        ldsm4(aL[ks], tile_addr(sQl, lane, m0, 32 * ks));
    }

    float s[8][4];
    #pragma unroll
    for (int j = 0; j < 8; j++)
        #pragma unroll
        for (int c = 0; c < 4; c++) s[j][c] = 0.0f;

    #pragma unroll
    for (int nt = 0; nt < 4; nt++) {
        uint32_t bh[2][4], bl[2][4];
        #pragma unroll
        for (int ks = 0; ks < 2; ks++) {
            ldsm4(bh[ks], tile_addr(sKh, lane, nt * 16, 32 * ks));
            ldsm4(bl[ks], tile_addr(sKl, lane, nt * 16, 32 * ks));
        }
        const int j0 = 2 * nt, j1 = 2 * nt + 1;
        #pragma unroll
        for (int ks = 0; ks < 2; ks++) {
            mma16816(s[j0], aH[ks], bh[ks][0], bh[ks][2]);
            mma16816(s[j1], aH[ks], bh[ks][1], bh[ks][3]);
            mma16816(s[j0], aH[ks], bl[ks][0], bl[ks][2]);
            mma16816(s[j1], aH[ks], bl[ks][1], bl[ks][3]);
            mma16816(s[j0], aL[ks], bh[ks][0], bh[ks][2]);
            mma16816(s[j1], aL[ks], bh[ks][1], bh[ks][3]);
        }
    }

    // ---- scale + position + softmax (rows r0, r1) ----
    const float sc = __expf(fminf(__ldg(ls + h), LOGIT_MAX));
    const float* pb = pos + ((long)(b * HH + h) * LLEN) * LLEN;

    float mx0 = -1e30f, mx1 = -1e30f;
    #pragma unroll
    for (int j = 0; j < 8; j++) {
        float2 p0 = *(const float2*)(pb + r0 * LLEN + j * 8 + t * 2);
        float2 p1 = *(const float2*)(pb + r1 * LLEN + j * 8 + t * 2);
        s[j][0] = fmaf(s[j][0], sc, p0.x);
        s[j][1] = fmaf(s[j][1], sc, p0.y);
        s[j][2] = fmaf(s[j][2], sc, p1.x);
        s[j][3] = fmaf(s[j][3], sc, p1.y);
        mx0 = fmaxf(mx0, fmaxf(s[j][0], s[j][1]));
        mx1 = fmaxf(mx1, fmaxf(s[j][2], s[j][3]));
    }
    mx0 = fmaxf(mx0, __shfl_xor_sync(0xffffffffu, mx0, 1));
    mx0 = fmaxf(mx0, __shfl_xor_sync(0xffffffffu, mx0, 2));
    mx1 = fmaxf(mx1, __shfl_xor_sync(0xffffffffu, mx1, 1));
    mx1 = fmaxf(mx1, __shfl_xor_sync(0xffffffffu, mx1, 2));

    float sum0 = 0.0f, sum1 = 0.0f;
    #pragma unroll
    for (int j = 0; j < 8; j++) {
        s[j][0] = __expf(s[j][0] - mx0);
        s[j][1] = __expf(s[j][1] - mx0);
        s[j][2] = __expf(s[j][2] - mx1);
        s[j][3] = __expf(s[j][3] - mx1);
        sum0 += s[j][0] + s[j][1];
        sum1 += s[j][2] + s[j][3];
    }
    sum0 += __shfl_xor_sync(0xffffffffu, sum0, 1);
    sum0 += __shfl_xor_sync(0xffffffffu, sum0, 2);
    sum1 += __shfl_xor_sync(0xffffffffu, sum1, 1);
    sum1 += __shfl_xor_sync(0xffffffffu, sum1, 2);
    const float inv0 = __fdividef(1.0f, sum0);
    const float inv1 = __fdividef(1.0f, sum1);

    // normalize + write attn (fp32 exact)
    float* attn = out + X_TOTAL + ((long)((b * NW + w) * HH + h)) * (LLEN * LLEN);
    #pragma unroll
    for (int j = 0; j < 8; j++) {
        s[j][0] *= inv0; s[j][1] *= inv0;
        s[j][2] *= inv1; s[j][3] *= inv1;
        *(float2*)(attn + r0 * LLEN + j * 8 + t * 2) = make_float2(s[j][0], s[j][1]);
        *(float2*)(attn + r1 * LLEN + j * 8 + t * 2) = make_float2(s[j][2], s[j][3]);
    }

    // ---- repack P fragments (C-layout == A-layout) with hi/lo split ----
    uint32_t pHi[4][4], pLo[4][4];
    #pragma unroll
    for (int kk = 0; kk < 4; kk++) {
        const int j0 = 2 * kk, j1 = 2 * kk + 1;
        pHi[kk][0] = pack2(s[j0][0], s[j0][1]);
        pHi[kk][1] = pack2(s[j0][2], s[j0][3]);
        pHi[kk][2] = pack2(s[j1][0], s[j1][1]);
        pHi[kk][3] = pack2(s[j1][2], s[j1][3]);
        float2 f;
        f = unpack2(pHi[kk][0]); pLo[kk][0] = pack2(s[j0][0] - f.x, s[j0][1] - f.y);
        f = unpack2(pHi[kk][1]); pLo[kk][1] = pack2(s[j0][2] - f.x, s[j0][3] - f.y);
        f = unpack2(pHi[kk][2]); pLo[kk][2] = pack2(s[j1][0] - f.x, s[j1][1] - f.y);
        f = unpack2(pHi[kk][3]); pLo[kk][3] = pack2(s[j1][2] - f.x, s[j1][3] - f.y);
    }

    // ---- O = P V (64x32x64); V fragments via ldmatrix.trans ----
    float* xo = out + qkvbase + h * DH;
    #pragma unroll
    for (int dt = 0; dt < 2; dt++) {
        float o0[4] = {0.f, 0.f, 0.f, 0.f};   // d-tile dt*16
        float o1[4] = {0.f, 0.f, 0.f, 0.f};   // d-tile dt*16+8
        #pragma unroll
        for (int ks = 0; ks < 4; ks++) {
            uint32_t vhf[4], vlf[4];
            ldsm4t(vhf, tile_addr(sVh, lane, ks * 16, 32 * dt));
            ldsm4t(vlf, tile_addr(sVl, lane, ks * 16, 32 * dt));
            mma16816(o0, pHi[ks], vhf[0], vhf[1]);
            mma16816(o1, pHi[ks], vhf[2], vhf[3]);
            mma16816(o0, pHi[ks], vlf[0], vlf[1]);
            mma16816(o1, pHi[ks], vlf[2], vlf[3]);
            mma16816(o0, pLo[ks], vhf[0], vhf[1]);
            mma16816(o1, pLo[ks], vhf[2], vhf[3]);
        }
        const int d0 = dt * 16 + t * 2;
        *(float2*)(xo + (long)r0 * CC + d0)     = make_float2(o0[0], o0[1]);
        *(float2*)(xo + (long)r1 * CC + d0)     = make_float2(o0[2], o0[3]);
        *(float2*)(xo + (long)r0 * CC + d0 + 8) = make_float2(o1[0], o1[1]);
        *(float2*)(xo + (long)r1 * CC + d0 + 8) = make_float2(o1[2], o1[3]);
    }
}

extern "C" void kernel_launch(void* const* d_in, const int* in_sizes, int n_in,
                              void* d_out, int out_size)
{
    const float* q   = (const float*)d_in[0];
    const float* k   = (const float*)d_in[1];
    const float* v   = (const float*)d_in[2];
    const float* pos = (const float*)d_in[3];
    const float* ls  = (const float*)d_in[4];
    float* out = (float*)d_out;

    dim3 grid(HH, NW, BB);   // 12800 CTAs
    tat_hmma_kernel<<<grid, 128>>>(q, k, v, pos, ls, out);
}